// round 15
// baseline (speedup 1.0000x reference)
#include <cuda_runtime.h>
#include <cuda_fp16.h>
#include <math.h>

#define Tt   64
#define Bb   128
#define Ee   1024
#define Hh   1024
#define Vv   10000
#define NBLK 12
#define GRID_R 128
#define VPAD 10112
#define PIPE 2

// ---------------- scratch (device globals) ----------------
__device__ __align__(16) float  g_XC[Tt*Bb*Hh];
__device__ __align__(16) float  g_XH[Tt*Bb*Hh];
__device__ __align__(16) float  g_OUT[Tt*Bb*Hh];    // tf32-rounded pre-clip hidden (decoder A)
__device__ __align__(16) __half g_Hh2[2*Bb*Hh];     // fp16 hidden, stage-parity double buffer
__device__ __align__(16) float  g_pss[Bb*128];      // per-(row, nt*2+wni) norm partials
__device__ __align__(16) __half g_Wc[NBLK*Hh*Hh];   // fp16 [w_hc, edge_c x11]  (gate)
__device__ __align__(16) __half g_Wh[NBLK*Hh*Hh];   // fp16 [w_hh, edge_h x11]  (candidate)
__device__ __align__(16) float  g_We[Vv*Ee];
__device__ __align__(16) float  g_Wx[2*Hh*Ee];
__device__ __align__(16) float  g_Wd[VPAD*Hh];
__device__ unsigned g_arr[GRID_R];
__device__ unsigned g_rel2[2];
__device__ unsigned g_wcnt[8];     // [mrow][chunk] write counters (16 producers each)
__device__ unsigned g_rarr[2];     // [mrow] read counters (64 per stage)

// ---------------- helpers ----------------
__device__ __forceinline__ unsigned f2tf32(float x){
  unsigned u; asm("cvt.rna.tf32.f32 %0, %1;" : "=r"(u) : "f"(x)); return u;
}
__device__ __forceinline__ float rndtf(float x){ return __uint_as_float(f2tf32(x)); }

__device__ __forceinline__ uint2 pack4h(float4 v){
  __half2 a = __floats2half2_rn(v.x, v.y);
  __half2 b = __floats2half2_rn(v.z, v.w);
  uint2 u;
  u.x = *(unsigned*)&a;
  u.y = *(unsigned*)&b;
  return u;
}

__device__ __forceinline__ void mma_tf32(float* c, const unsigned* a, const unsigned* b){
  asm volatile(
    "mma.sync.aligned.m16n8k8.row.col.f32.tf32.tf32.f32 "
    "{%0,%1,%2,%3}, {%4,%5,%6,%7}, {%8,%9}, {%0,%1,%2,%3};\n"
    : "+f"(c[0]), "+f"(c[1]), "+f"(c[2]), "+f"(c[3])
    : "r"(a[0]), "r"(a[1]), "r"(a[2]), "r"(a[3]), "r"(b[0]), "r"(b[1]));
}

__device__ __forceinline__ void mma_fp16(float* c, const unsigned* a, const unsigned* b){
  asm volatile(
    "mma.sync.aligned.m16n8k16.row.col.f32.f16.f16.f32 "
    "{%0,%1,%2,%3}, {%4,%5,%6,%7}, {%8,%9}, {%0,%1,%2,%3};\n"
    : "+f"(c[0]), "+f"(c[1]), "+f"(c[2]), "+f"(c[3])
    : "r"(a[0]), "r"(a[1]), "r"(a[2]), "r"(a[3]), "r"(b[0]), "r"(b[1]));
}

__device__ __forceinline__ void ldsm4(unsigned* r, unsigned a){
  asm volatile("ldmatrix.sync.aligned.m8n8.x4.shared.b16 {%0,%1,%2,%3}, [%4];"
    : "=r"(r[0]), "=r"(r[1]), "=r"(r[2]), "=r"(r[3]) : "r"(a));
}

__device__ __forceinline__ void cpa16(void* smemp, const void* gmem){
  unsigned s = (unsigned)__cvta_generic_to_shared(smemp);
  asm volatile("cp.async.cg.shared.global [%0], [%1], 16;\n" :: "r"(s), "l"(gmem));
}
__device__ __forceinline__ void cpa_commit(){ asm volatile("cp.async.commit_group;\n"); }
template<int N> __device__ __forceinline__ void cpa_wait(){
  asm volatile("cp.async.wait_group %0;\n" :: "n"(N));
}

__device__ __forceinline__ float sigm(float x){ return 1.f/(1.f + expf(-x)); }

// group barrier: 64 CTAs of the same mrow. Used only for init + per-timestep clip.
__device__ __forceinline__ void gsyncg(unsigned &ep, int mrow, int lid){
  ep++;
  __syncthreads();
  if (lid == 0){
    if (threadIdx.x > 0 && threadIdx.x < 64){
      while (*(volatile unsigned*)&g_arr[mrow*64 + threadIdx.x] < ep) { }
    }
    __syncthreads();
    if (threadIdx.x == 0){ __threadfence(); *(volatile unsigned*)&g_rel2[mrow] = ep; }
  } else {
    if (threadIdx.x == 0){
      __threadfence();
      *(volatile unsigned*)&g_arr[mrow*64 + lid] = ep;
      while (*(volatile unsigned*)&g_rel2[mrow] < ep) { }
    }
  }
  __syncthreads();
  __threadfence();
}

// tf32 warp tile 64x32 (mi4 x ni4), k-block 32 floats, smem row stride 36 u32
__device__ __forceinline__ void compute_64x32(const float* Af, const float* Bf,
      float acc[4][4][4], int wm, int wn, int g, int tg){
  const unsigned* As = (const unsigned*)Af;
  const unsigned* Bs = (const unsigned*)Bf;
#pragma unroll
  for (int ks = 0; ks < 32; ks += 8){
    unsigned a[4][4], b[4][2];
#pragma unroll
    for (int mi = 0; mi < 4; mi++){
      int r = wm + mi*16 + g;
      a[mi][0] = As[r*36 + ks+tg];
      a[mi][1] = As[(r+8)*36 + ks+tg];
      a[mi][2] = As[r*36 + ks+tg+4];
      a[mi][3] = As[(r+8)*36 + ks+tg+4];
    }
#pragma unroll
    for (int ni = 0; ni < 4; ni++){
      int rr = wn + ni*8 + g;
      b[ni][0] = Bs[rr*36 + ks+tg];
      b[ni][1] = Bs[rr*36 + ks+tg+4];
    }
#pragma unroll
    for (int mi = 0; mi < 4; mi++)
#pragma unroll
      for (int ni = 0; ni < 4; ni++)
        mma_tf32(acc[mi][ni], a[mi], b[ni]);
  }
}

// fp16: one 64-k block via ldmatrix, warp tile 16(M)x8(N), both mats share A fragments.
__device__ __forceinline__ void compute_blk_ldsm(unsigned abase, unsigned cbase, unsigned hbase,
      float accc[4], float acch[4]){
  unsigned a[4][4];
#pragma unroll
  for (int ks = 0; ks < 4; ks++) ldsm4(a[ks], abase + ks*32);
  unsigned qc[2][4], qh[2][4];
  ldsm4(qc[0], cbase);
  ldsm4(qc[1], cbase + 64);
  ldsm4(qh[0], hbase);
  ldsm4(qh[1], hbase + 64);
#pragma unroll
  for (int ks = 0; ks < 4; ks++){
    mma_fp16(accc, a[ks], &qc[ks>>1][(ks&1)*2]);
    mma_fp16(acch, a[ks], &qh[ks>>1][(ks&1)*2]);
  }
}

// ---------------- prep: wc/wh -> fp16, we/wx/wd -> tf32 ----------------
#define S_WC  3145728L
#define S_WH  3145728L
#define S_WE  2560000L
#define S_WX   524288L
#define S_WD  2588672L
__global__ void __launch_bounds__(256) prep_all(
    const float* __restrict__ w_hc, const float* __restrict__ edge_c,
    const float* __restrict__ w_hh, const float* __restrict__ edge_h,
    const float* __restrict__ embW, const float* __restrict__ wxcW,
    const float* __restrict__ wxhW, const float* __restrict__ decW)
{
  long i = (long)blockIdx.x*256 + threadIdx.x;
  const long F4 = (long)Hh*Hh/4;
  if (i < S_WC){
    float4 v = (i < F4) ? ((const float4*)w_hc)[i] : ((const float4*)edge_c)[i-F4];
    ((uint2*)g_Wc)[i] = pack4h(v);
    return;
  }
  if ((i -= S_WC) < S_WH){
    float4 v = (i < F4) ? ((const float4*)w_hh)[i] : ((const float4*)edge_h)[i-F4];
    ((uint2*)g_Wh)[i] = pack4h(v);
    return;
  }
  float4 v; float4* dst;
  if ((i -= S_WH) < S_WE){
    v = ((const float4*)embW)[i];
    dst = ((float4*)g_We) + i;
  } else if ((i -= S_WE) < S_WX){
    const long G4 = (long)Hh*Ee/4;
    v = (i < G4) ? ((const float4*)wxcW)[i] : ((const float4*)wxhW)[i-G4];
    dst = ((float4*)g_Wx) + i;
  } else if ((i -= S_WX) < S_WD){
    long row = (i*4) >> 10;
    v = (row < Vv) ? ((const float4*)decW)[i] : make_float4(0.f,0.f,0.f,0.f);
    dst = ((float4*)g_Wd) + i;
  } else return;
  float4 r; r.x=rndtf(v.x); r.y=rndtf(v.y); r.z=rndtf(v.z); r.w=rndtf(v.w);
  *dst = r;
}

// ---------------- phase 1: input projections (tf32) ----------------
__global__ void __launch_bounds__(256) xproj_kernel(
    const int* __restrict__ tokens,
    const float* __restrict__ wxcB, const float* __restrict__ wxhB)
{
  extern __shared__ unsigned char smraw[];
  float* Ash = (float*)smraw;
  float* Bsh = (float*)smraw + PIPE*4608;
  __shared__ int toks[128];
  const int tid = threadIdx.x;
  const int n0 = blockIdx.x * 128;
  const int m0 = blockIdx.y * 128;
  const int mat = blockIdx.z;
  const float* W    = g_Wx + (size_t)mat*Hh*Ee;
  const float* bias = mat ? wxhB : wxcB;
  float* Cout = mat ? g_XH : g_XC;
  if (tid < 128) toks[tid] = tokens[m0 + tid];
  __syncthreads();
  const int lane = tid & 31, warp = tid >> 5;
  const int wm = (warp & 1) * 64, wn = (warp >> 1) * 32;
  const int g = lane >> 2, tg = lane & 3;

  float acc[4][4][4];
#pragma unroll
  for (int a=0;a<4;a++)
#pragma unroll
    for (int b=0;b<4;b++)
#pragma unroll
      for (int c=0;c<4;c++) acc[a][b][c]=0.f;

  auto load_tile = [&](int p, int kbi){
    int kb = kbi * 32;
#pragma unroll
    for (int i = 0; i < 4; i++){
      int idx = tid + i*256, row = idx>>3, c4 = (idx&7)*4;
      cpa16(&Ash[p*4608 + row*36 + c4], g_We + (size_t)toks[row]*Ee + kb + c4);
      cpa16(&Bsh[p*4608 + row*36 + c4], W + (size_t)(n0+row)*Ee + kb + c4);
    }
  };

#pragma unroll
  for (int p = 0; p < PIPE-1; p++){ load_tile(p, p); cpa_commit(); }
  for (int it = 0; it < 32; it++){
    cpa_wait<PIPE-2>();
    __syncthreads();
    int nx = it + PIPE - 1;
    if (nx < 32) load_tile(nx % PIPE, nx);
    cpa_commit();
    compute_64x32(Ash + (it%PIPE)*4608, Bsh + (it%PIPE)*4608, acc, wm, wn, g, tg);
  }

#pragma unroll
  for (int mi=0; mi<4; mi++){
    int r = m0 + wm + mi*16 + g;
#pragma unroll
    for (int ni=0; ni<4; ni++){
      int c = n0 + wn + ni*8 + 2*tg;
      float b0 = bias[c], b1 = bias[c+1];
      size_t o = (size_t)r*Hh + c;
      Cout[o]        = acc[mi][ni][0] + b0;
      Cout[o+1]      = acc[mi][ni][1] + b1;
      Cout[o+8*Hh]   = acc[mi][ni][2] + b0;
      Cout[o+8*Hh+1] = acc[mi][ni][3] + b1;
    }
  }
}

// ---------------- phase 2: persistent recurrence ----------------
// 128 CTAs = 2 mrow x 64 nt. CTA: rows [mrow*64,+64), cols [nt*16,+16), BOTH mats, K=1024.
// Chunk-granular producer/consumer flags instead of per-stage barriers:
//   - A-chunk c of stage K needs only the 16 CTAs nt in [16c,16c+16) (same mrow)
//     to have published stage K-1's h  -> poll g_wcnt[mrow*4+c] >= 16*(K-1).
//   - WAR guard before overwriting the h buffer read in stage K-1:
//     poll g_rarr[mrow] >= 64*(K-1); each CTA arrives after its last cpa_wait.
__global__ void __launch_bounds__(256) rnn_kernel(float* __restrict__ outp)
{
  extern __shared__ unsigned char smraw[];
  __half* Aw = (__half*)smraw;               // 2 x 18432 halves
  __half* Bw = (__half*)smraw + 2*18432;     // 2 x 36864 halves
  const int tid = threadIdx.x;
  const int bid = blockIdx.x;
  const int lane = tid & 31, warp = tid >> 5;
  const int wm = (warp & 3) * 16;
  const int wn = (warp >> 2) * 8;
  const int wni = warp >> 2;
  const int g = lane >> 2, tg = lane & 3;
  const int mrow = bid >> 6;
  const int nt   = bid & 63;
  const int rbase = mrow * 64;
  const int n0 = nt * 16;
  const int r0 = rbase + wm + g, r1 = r0 + 8;
  const int c0 = n0 + wn + 2*tg;
  const int mychunk = mrow*4 + (nt >> 4);
  unsigned ep = 0;

  const unsigned sA = (unsigned)__cvta_generic_to_shared(Aw);
  const unsigned sB = (unsigned)__cvta_generic_to_shared(Bw);
  const int lj = lane >> 3, lr = lane & 7;
  const unsigned aoff = (unsigned)(((wm + lr + ((lj&1)<<3))*72 + ((lj>>1)<<3)) * 2);
  const unsigned boff = (unsigned)(((wn + lr)*72 + lj*8) * 2);

  auto load_A = [&](int par, int kb, int p){   // chunk kb (0..3): 64 rows x 256 k
    const __half* src = g_Hh2 + (size_t)par*Bb*Hh + (size_t)rbase*Hh;
#pragma unroll
    for (int i = 0; i < 8; i++){
      int idx = tid + i*256;
      int row = idx >> 5;
      int kh  = (idx & 31) * 8;
      int blk = kh >> 6, kk = kh & 63;
      cpa16(&Aw[p*18432 + blk*4608 + row*72 + kk],
            src + (size_t)row*Hh + kb*256 + kh);
    }
  };
  auto load_B = [&](int s, int q){
#pragma unroll
    for (int i = 0; i < 16; i++){
      int idx = tid + i*256;
      int m2 = idx >> 11;
      int j  = idx & 2047;
      int blk = j >> 7;
      int jj = j & 127;
      int row = jj >> 3, c8 = (jj & 7) * 8;
      const __half* W = (m2 ? g_Wh : g_Wc) + (size_t)s*Hh*Hh;
      cpa16(&Bw[q*36864 + m2*18432 + blk*1152 + row*72 + c8],
            W + (size_t)(n0+row)*Hh + blk*64 + c8);
    }
  };

  // poll helpers (thread 0 spins, then CTA-wide sync)
  auto wait_w = [&](int chunk, unsigned target){
    if (tid == 0){
      while (*(volatile unsigned*)&g_wcnt[mrow*4 + chunk] < target) { }
      __threadfence();
    }
    __syncthreads();
  };
  auto wait_r = [&](unsigned target){
    if (tid == 0){
      while (*(volatile unsigned*)&g_rarr[mrow] < target) { }
      __threadfence();
    }
    __syncthreads();
  };

  float hp0 = 0.f, hp1 = 0.f, hp2 = 0.f, hp3 = 0.f;

  load_B(0, 0); cpa_commit();
  {
    uint2 z; z.x = 0u; z.y = 0u;
    ((uint2*)g_Hh2)[bid*256 + tid] = z;        // buffer 0 zeros
  }
  gsyncg(ep, mrow, nt);

  unsigned K = 0;
  for (int t = 0; t < Tt; t++){
    for (int s = 0; s < NBLK; s++){
      K++;                                       // 1-based global stage index
      const unsigned wtgt = 16u * (K - 1u);
      const unsigned rtgt = 64u * (K - 1u);
      const int par = s & 1;
      const unsigned cbB = sB + (unsigned)(par*36864*2) + boff;
      const unsigned hbB = cbB + (unsigned)(18432*2);

      float accc[4] = {0.f,0.f,0.f,0.f};
      float acch[4] = {0.f,0.f,0.f,0.f};

      wait_w(0, wtgt);
      load_A(par, 0, 0); cpa_commit();
      wait_w(1, wtgt);
      load_A(par, 1, 1); cpa_commit();
      {
        int sn = s + 1; if (sn == NBLK) sn = 0;
        load_B(sn, par ^ 1); cpa_commit();
      }

      // chunk 0
      cpa_wait<2>(); __syncthreads();
#pragma unroll
      for (int b = 0; b < 4; b++)
        compute_blk_ldsm(sA + (unsigned)(0*18432 + b*4608)*2 + aoff,
                         cbB + (unsigned)((0*4+b)*1152)*2,
                         hbB + (unsigned)((0*4+b)*1152)*2, accc, acch);
      __syncthreads();
      wait_w(2, wtgt);
      load_A(par, 2, 0); cpa_commit();

      // chunk 1
      cpa_wait<2>(); __syncthreads();
#pragma unroll
      for (int b = 0; b < 4; b++)
        compute_blk_ldsm(sA + (unsigned)(1*18432 + b*4608)*2 + aoff,
                         cbB + (unsigned)((1*4+b)*1152)*2,
                         hbB + (unsigned)((1*4+b)*1152)*2, accc, acch);
      __syncthreads();
      wait_w(3, wtgt);
      load_A(par, 3, 1); cpa_commit();

      // chunk 2
      cpa_wait<1>(); __syncthreads();
#pragma unroll
      for (int b = 0; b < 4; b++)
        compute_blk_ldsm(sA + (unsigned)(0*18432 + b*4608)*2 + aoff,
                         cbB + (unsigned)((2*4+b)*1152)*2,
                         hbB + (unsigned)((2*4+b)*1152)*2, accc, acch);

      // chunk 3 (wait<0> also covers next-stage B); then publish read-completion
      cpa_wait<0>(); __syncthreads();
      if (tid == 0) atomicAdd(&g_rarr[mrow], 1u);
#pragma unroll
      for (int b = 0; b < 4; b++)
        compute_blk_ldsm(sA + (unsigned)(1*18432 + b*4608)*2 + aoff,
                         cbB + (unsigned)((3*4+b)*1152)*2,
                         hbB + (unsigned)((3*4+b)*1152)*2, accc, acch);

      // fused epilogue
      {
        const int np = par ^ 1;
        __half* Hh16 = g_Hh2 + (size_t)np*Bb*Hh;

        float sc0=accc[0], sc1=accc[1], sc2=accc[2], sc3=accc[3];
        float sh0=acch[0], sh1=acch[1], sh2=acch[2], sh3=acch[3];
        if (s == 0){
          const float* XCb = g_XC + ((size_t)t<<17);
          const float* XHb = g_XH + ((size_t)t<<17);
          float2 a0 = *(const float2*)(XCb + (size_t)r0*Hh + c0);
          float2 a1 = *(const float2*)(XCb + (size_t)r1*Hh + c0);
          float2 b0 = *(const float2*)(XHb + (size_t)r0*Hh + c0);
          float2 b1 = *(const float2*)(XHb + (size_t)r1*Hh + c0);
          sc0 += a0.x; sc1 += a0.y; sc2 += a1.x; sc3 += a1.y;
          sh0 += b0.x; sh1 += b0.y; sh2 += b1.x; sh3 += b1.y;
        }
        const bool use_tanh = (s == 0) || (s & 1);
        float g0 = sigm(sc0), g1 = sigm(sc1), g2 = sigm(sc2), g3 = sigm(sc3);
        float a0 = use_tanh ? tanhf(sh0) : fmaxf(sh0, 0.f);
        float a1 = use_tanh ? tanhf(sh1) : fmaxf(sh1, 0.f);
        float a2 = use_tanh ? tanhf(sh2) : fmaxf(sh2, 0.f);
        float a3 = use_tanh ? tanhf(sh3) : fmaxf(sh3, 0.f);
        float n0v = g0*a0 + (1.f-g0)*hp0;
        float n1v = g1*a1 + (1.f-g1)*hp1;
        float n2v = g2*a2 + (1.f-g2)*hp2;
        float n3v = g3*a3 + (1.f-g3)*hp3;

        if (s < NBLK-1){
          hp0 = n0v; hp1 = n1v; hp2 = n2v; hp3 = n3v;
          wait_r(rtgt);                      // WAR guard (passes instantly in steady state)
          __half2 p0 = __floats2half2_rn(n0v, n1v);
          __half2 p1 = __floats2half2_rn(n2v, n3v);
          *(unsigned*)(Hh16 + (size_t)r0*Hh + c0) = *(unsigned*)&p0;
          *(unsigned*)(Hh16 + (size_t)r1*Hh + c0) = *(unsigned*)&p1;
          __syncthreads();
          if (tid == 0){ __threadfence(); atomicAdd(&g_wcnt[mychunk], 1u); }
        } else {
          float* Ob = g_OUT + ((size_t)t<<17);
          *(float2*)(Ob + (size_t)r0*Hh + c0) = make_float2(rndtf(n0v), rndtf(n1v));
          *(float2*)(Ob + (size_t)r1*Hh + c0) = make_float2(rndtf(n2v), rndtf(n3v));
          float ss0 = n0v*n0v + n1v*n1v;
          float ss1 = n2v*n2v + n3v*n3v;
          ss0 += __shfl_xor_sync(0xffffffffu, ss0, 1);
          ss0 += __shfl_xor_sync(0xffffffffu, ss0, 2);
          ss1 += __shfl_xor_sync(0xffffffffu, ss1, 1);
          ss1 += __shfl_xor_sync(0xffffffffu, ss1, 2);
          if (tg == 0){
            g_pss[r0*128 + nt*2 + wni] = ss0;
            g_pss[r1*128 + nt*2 + wni] = ss1;
          }
          gsyncg(ep, mrow, nt);              // all partials + all K-1 reads complete
          float t0 = 0.f, t1 = 0.f;
          const float4* q0 = (const float4*)(g_pss + (size_t)r0*128);
          const float4* q1 = (const float4*)(g_pss + (size_t)r1*128);
#pragma unroll
          for (int j = 0; j < 32; j++){
            float4 v = q0[j]; t0 += v.x + v.y + v.z + v.w;
            float4 w = q1[j]; t1 += w.x + w.y + w.z + w.w;
          }
          float nm0 = sqrtf(t0), nm1 = sqrtf(t1);
          float sA0 = (nm0 > 25.f) ? (25.f / nm0) : 1.f;
          float sA1 = (nm1 > 25.f) ? (25.f / nm1) : 1.f;
          hp0 = n0v * sA0; hp1 = n1v * sA0;
          hp2 = n2v * sA1; hp3 = n3v * sA1;
          __half2 p0 = __floats2half2_rn(hp0, hp1);
          __half2 p1 = __floats2half2_rn(hp2, hp3);
          *(unsigned*)(Hh16 + (size_t)r0*Hh + c0) = *(unsigned*)&p0;
          *(unsigned*)(Hh16 + (size_t)r1*Hh + c0) = *(unsigned*)&p1;
          __syncthreads();
          if (tid == 0){ __threadfence(); atomicAdd(&g_wcnt[mychunk], 1u); }
        }
      }
    }
  }

  // hT (clipped final hidden, from registers)
  {
    float* o = outp + (size_t)Tt*Bb*Vv;
    *(float2*)(o + (size_t)r0*Hh + c0) = make_float2(hp0, hp1);
    *(float2*)(o + (size_t)r1*Hh + c0) = make_float2(hp2, hp3);
  }
}

// ---------------- phase 3: decoder GEMM (tf32) ----------------
__global__ void __launch_bounds__(256) dec_kernel(
  const float* __restrict__ decB, float* __restrict__ outp)
{
  extern __shared__ unsigned char smraw[];
  float* Ash = (float*)smraw;
  float* Bsh = (float*)smraw + PIPE*4608;
  const int tid = threadIdx.x;
  const int n0 = blockIdx.x * 128;
  const int m0 = blockIdx.y * 128;
  const int lane = tid & 31, warp = tid >> 5;
  const int wm = (warp & 1) * 64, wn = (warp >> 1) * 32;
  const int g = lane >> 2, tg = lane & 3;
  float acc[4][4][4];
#pragma unroll
  for (int a=0;a<4;a++)
#pragma unroll
    for (int b=0;b<4;b++)
#pragma unroll
      for (int c=0;c<4;c++) acc[a][b][c]=0.f;

  auto load_tile = [&](int p, int kbi){
    int kb = kbi * 32;
#pragma unroll
    for (int i = 0; i < 4; i++){
      int idx = tid + i*256, row = idx>>3, c4 = (idx&7)*4;
      cpa16(&Ash[p*4608 + row*36 + c4], g_OUT + (size_t)(m0+row)*Hh + kb + c4);
      cpa16(&Bsh[p*4608 + row*36 + c4], g_Wd + (size_t)(n0+row)*Hh + kb + c4);
    }
  };

#pragma unroll
  for (int p = 0; p < PIPE-1; p++){ load_tile(p, p); cpa_commit(); }
  for (int it = 0; it < 32; it++){
    cpa_wait<PIPE-2>();
    __syncthreads();
    int nx = it + PIPE - 1;
    if (nx < 32) load_tile(nx % PIPE, nx);
    cpa_commit();
    compute_64x32(Ash + (it%PIPE)*4608, Bsh + (it%PIPE)*4608, acc, wm, wn, g, tg);
  }

#pragma unroll
  for (int mi=0;mi<4;mi++){
    int r = m0 + wm + mi*16 + g;
#pragma unroll
    for (int ni=0;ni<4;ni++){
      int c = n0 + wn + ni*8 + 2*tg;
      if (c < Vv){
        float b0 = decB[c], b1 = decB[c+1];
        size_t o  = (size_t)r*Vv + c;
        size_t o2 = o + (size_t)8*Vv;
        outp[o]    = acc[mi][ni][0] + b0;
        outp[o+1]  = acc[mi][ni][1] + b1;
        outp[o2]   = acc[mi][ni][2] + b0;
        outp[o2+1] = acc[mi][ni][3] + b1;
      }
    }
  }
}

// ---------------- launch ----------------
extern "C" void kernel_launch(void* const* d_in, const int* in_sizes, int n_in,
                              void* d_out, int out_size){
  const int*   tokens = (const int*)  d_in[0];
  const float* embW   = (const float*)d_in[1];
  const float* wxcW   = (const float*)d_in[2];
  const float* wxcB   = (const float*)d_in[3];
  const float* wxhW   = (const float*)d_in[4];
  const float* wxhB   = (const float*)d_in[5];
  const float* w_hc   = (const float*)d_in[6];
  const float* w_hh   = (const float*)d_in[7];
  const float* edge_h = (const float*)d_in[8];
  const float* edge_c = (const float*)d_in[9];
  const float* decW   = (const float*)d_in[10];
  const float* decB   = (const float*)d_in[11];
  float* outp = (float*)d_out;
  (void)in_sizes; (void)n_in; (void)out_size;

  const int RNN_SMEM  = (2*18432 + 2*36864) * 2;   // 221184 B
  const int GEMM_SMEM = PIPE * 2 * 4608 * 4;       // 73728 B
  cudaFuncSetAttribute(xproj_kernel, cudaFuncAttributeMaxDynamicSharedMemorySize, GEMM_SMEM);
  cudaFuncSetAttribute(rnn_kernel,   cudaFuncAttributeMaxDynamicSharedMemorySize, RNN_SMEM);
  cudaFuncSetAttribute(dec_kernel,   cudaFuncAttributeMaxDynamicSharedMemorySize, GEMM_SMEM);

  // reset barrier flags + counters
  void *pArr = nullptr, *pRel = nullptr, *pW = nullptr, *pR = nullptr;
  cudaGetSymbolAddress(&pArr, g_arr);
  cudaGetSymbolAddress(&pRel, g_rel2);
  cudaGetSymbolAddress(&pW,   g_wcnt);
  cudaGetSymbolAddress(&pR,   g_rarr);
  cudaMemsetAsync(pArr, 0, sizeof(unsigned)*GRID_R);
  cudaMemsetAsync(pRel, 0, sizeof(unsigned)*2);
  cudaMemsetAsync(pW,   0, sizeof(unsigned)*8);
  cudaMemsetAsync(pR,   0, sizeof(unsigned)*2);

  const long PREP_TOTAL = S_WC + S_WH + S_WE + S_WX + S_WD;
  prep_all<<<(unsigned)((PREP_TOTAL + 255) / 256), 256>>>(
      w_hc, edge_c, w_hh, edge_h, embW, wxcW, wxhW, decW);

  xproj_kernel<<<dim3(8, 64, 2), 256, GEMM_SMEM>>>(tokens, wxcB, wxhB);
  rnn_kernel<<<GRID_R, 256, RNN_SMEM>>>(outp);
  dec_kernel<<<dim3(VPAD/128, 64), 256, GEMM_SMEM>>>(decB, outp);
}

// round 16
// speedup vs baseline: 1.2012x; 1.2012x over previous
#include <cuda_runtime.h>
#include <cuda_fp16.h>
#include <math.h>

#define Tt   64
#define Bb   128
#define Ee   1024
#define Hh   1024
#define Vv   10000
#define NBLK 12
#define GRID_R 128
#define VPAD 10112
#define PIPE 2

// ---------------- scratch (device globals) ----------------
__device__ __align__(16) float  g_XC[Tt*Bb*Hh];
__device__ __align__(16) float  g_XH[Tt*Bb*Hh];
__device__ __align__(16) float  g_OUT[Tt*Bb*Hh];    // tf32-rounded pre-clip hidden (decoder A)
__device__ __align__(16) __half g_Hh2[2*Bb*Hh];     // fp16 hidden, stage-parity double buffer
__device__ __align__(16) float  g_pss[Bb*128];      // per-(row, nt*2+wni) norm partials
__device__ __align__(16) __half g_Wc[NBLK*Hh*Hh];   // fp16 [w_hc, edge_c x11]  (gate)
__device__ __align__(16) __half g_Wh[NBLK*Hh*Hh];   // fp16 [w_hh, edge_h x11]  (candidate)
__device__ __align__(16) float  g_We[Vv*Ee];
__device__ __align__(16) float  g_Wx[2*Hh*Ee];
__device__ __align__(16) float  g_Wd[VPAD*Hh];
__device__ unsigned g_arr[GRID_R];
__device__ unsigned g_rel2[2];

// ---------------- helpers ----------------
__device__ __forceinline__ unsigned f2tf32(float x){
  unsigned u; asm("cvt.rna.tf32.f32 %0, %1;" : "=r"(u) : "f"(x)); return u;
}
__device__ __forceinline__ float rndtf(float x){ return __uint_as_float(f2tf32(x)); }

__device__ __forceinline__ uint2 pack4h(float4 v){
  __half2 a = __floats2half2_rn(v.x, v.y);
  __half2 b = __floats2half2_rn(v.z, v.w);
  uint2 u;
  u.x = *(unsigned*)&a;
  u.y = *(unsigned*)&b;
  return u;
}

__device__ __forceinline__ void mma_tf32(float* c, const unsigned* a, const unsigned* b){
  asm volatile(
    "mma.sync.aligned.m16n8k8.row.col.f32.tf32.tf32.f32 "
    "{%0,%1,%2,%3}, {%4,%5,%6,%7}, {%8,%9}, {%0,%1,%2,%3};\n"
    : "+f"(c[0]), "+f"(c[1]), "+f"(c[2]), "+f"(c[3])
    : "r"(a[0]), "r"(a[1]), "r"(a[2]), "r"(a[3]), "r"(b[0]), "r"(b[1]));
}

__device__ __forceinline__ void mma_fp16(float* c, const unsigned* a, const unsigned* b){
  asm volatile(
    "mma.sync.aligned.m16n8k16.row.col.f32.f16.f16.f32 "
    "{%0,%1,%2,%3}, {%4,%5,%6,%7}, {%8,%9}, {%0,%1,%2,%3};\n"
    : "+f"(c[0]), "+f"(c[1]), "+f"(c[2]), "+f"(c[3])
    : "r"(a[0]), "r"(a[1]), "r"(a[2]), "r"(a[3]), "r"(b[0]), "r"(b[1]));
}

__device__ __forceinline__ void ldsm4(unsigned* r, unsigned a){
  asm volatile("ldmatrix.sync.aligned.m8n8.x4.shared.b16 {%0,%1,%2,%3}, [%4];"
    : "=r"(r[0]), "=r"(r[1]), "=r"(r[2]), "=r"(r[3]) : "r"(a));
}

__device__ __forceinline__ void cpa16(void* smemp, const void* gmem){
  unsigned s = (unsigned)__cvta_generic_to_shared(smemp);
  asm volatile("cp.async.cg.shared.global [%0], [%1], 16;\n" :: "r"(s), "l"(gmem));
}
__device__ __forceinline__ void cpa_commit(){ asm volatile("cp.async.commit_group;\n"); }
template<int N> __device__ __forceinline__ void cpa_wait(){
  asm volatile("cp.async.wait_group %0;\n" :: "n"(N));
}

__device__ __forceinline__ float sigm(float x){ return 1.f/(1.f + expf(-x)); }

// group barrier: 64 CTAs of the same mrow (recurrence is row-independent).
__device__ __forceinline__ void gsyncg(unsigned &ep, int mrow, int lid){
  ep++;
  __syncthreads();
  if (lid == 0){
    if (threadIdx.x > 0 && threadIdx.x < 64){
      while (*(volatile unsigned*)&g_arr[mrow*64 + threadIdx.x] < ep) { }
    }
    __syncthreads();
    if (threadIdx.x == 0){ __threadfence(); *(volatile unsigned*)&g_rel2[mrow] = ep; }
  } else {
    if (threadIdx.x == 0){
      __threadfence();
      *(volatile unsigned*)&g_arr[mrow*64 + lid] = ep;
      while (*(volatile unsigned*)&g_rel2[mrow] < ep) { }
    }
  }
  __syncthreads();
  __threadfence();
}

// tf32 warp tile 64x32 (mi4 x ni4), k-block 32 floats, smem row stride 36 u32
__device__ __forceinline__ void compute_64x32(const float* Af, const float* Bf,
      float acc[4][4][4], int wm, int wn, int g, int tg){
  const unsigned* As = (const unsigned*)Af;
  const unsigned* Bs = (const unsigned*)Bf;
#pragma unroll
  for (int ks = 0; ks < 32; ks += 8){
    unsigned a[4][4], b[4][2];
#pragma unroll
    for (int mi = 0; mi < 4; mi++){
      int r = wm + mi*16 + g;
      a[mi][0] = As[r*36 + ks+tg];
      a[mi][1] = As[(r+8)*36 + ks+tg];
      a[mi][2] = As[r*36 + ks+tg+4];
      a[mi][3] = As[(r+8)*36 + ks+tg+4];
    }
#pragma unroll
    for (int ni = 0; ni < 4; ni++){
      int rr = wn + ni*8 + g;
      b[ni][0] = Bs[rr*36 + ks+tg];
      b[ni][1] = Bs[rr*36 + ks+tg+4];
    }
#pragma unroll
    for (int mi = 0; mi < 4; mi++)
#pragma unroll
      for (int ni = 0; ni < 4; ni++)
        mma_tf32(acc[mi][ni], a[mi], b[ni]);
  }
}

// fp16: one 64-k block via ldmatrix, warp tile 16(M)x8(N), both mats share A fragments.
__device__ __forceinline__ void compute_blk_ldsm(unsigned abase, unsigned cbase, unsigned hbase,
      float accc[4], float acch[4]){
  unsigned a[4][4];
#pragma unroll
  for (int ks = 0; ks < 4; ks++) ldsm4(a[ks], abase + ks*32);
  unsigned qc[2][4], qh[2][4];
  ldsm4(qc[0], cbase);
  ldsm4(qc[1], cbase + 64);
  ldsm4(qh[0], hbase);
  ldsm4(qh[1], hbase + 64);
#pragma unroll
  for (int ks = 0; ks < 4; ks++){
    mma_fp16(accc, a[ks], &qc[ks>>1][(ks&1)*2]);
    mma_fp16(acch, a[ks], &qh[ks>>1][(ks&1)*2]);
  }
}

// ---------------- prep: wc/wh -> fp16, we/wx/wd -> tf32 ----------------
#define S_WC  3145728L
#define S_WH  3145728L
#define S_WE  2560000L
#define S_WX   524288L
#define S_WD  2588672L
__global__ void __launch_bounds__(256) prep_all(
    const float* __restrict__ w_hc, const float* __restrict__ edge_c,
    const float* __restrict__ w_hh, const float* __restrict__ edge_h,
    const float* __restrict__ embW, const float* __restrict__ wxcW,
    const float* __restrict__ wxhW, const float* __restrict__ decW)
{
  long i = (long)blockIdx.x*256 + threadIdx.x;
  const long F4 = (long)Hh*Hh/4;
  if (i < S_WC){
    float4 v = (i < F4) ? ((const float4*)w_hc)[i] : ((const float4*)edge_c)[i-F4];
    ((uint2*)g_Wc)[i] = pack4h(v);
    return;
  }
  if ((i -= S_WC) < S_WH){
    float4 v = (i < F4) ? ((const float4*)w_hh)[i] : ((const float4*)edge_h)[i-F4];
    ((uint2*)g_Wh)[i] = pack4h(v);
    return;
  }
  float4 v; float4* dst;
  if ((i -= S_WH) < S_WE){
    v = ((const float4*)embW)[i];
    dst = ((float4*)g_We) + i;
  } else if ((i -= S_WE) < S_WX){
    const long G4 = (long)Hh*Ee/4;
    v = (i < G4) ? ((const float4*)wxcW)[i] : ((const float4*)wxhW)[i-G4];
    dst = ((float4*)g_Wx) + i;
  } else if ((i -= S_WX) < S_WD){
    long row = (i*4) >> 10;
    v = (row < Vv) ? ((const float4*)decW)[i] : make_float4(0.f,0.f,0.f,0.f);
    dst = ((float4*)g_Wd) + i;
  } else return;
  float4 r; r.x=rndtf(v.x); r.y=rndtf(v.y); r.z=rndtf(v.z); r.w=rndtf(v.w);
  *dst = r;
}

// ---------------- phase 1: input projections (tf32) ----------------
__global__ void __launch_bounds__(256, 2) xproj_kernel(
    const int* __restrict__ tokens,
    const float* __restrict__ wxcB, const float* __restrict__ wxhB)
{
  extern __shared__ unsigned char smraw[];
  float* Ash = (float*)smraw;
  float* Bsh = (float*)smraw + PIPE*4608;
  __shared__ int toks[128];
  const int tid = threadIdx.x;
  const int n0 = blockIdx.x * 128;
  const int m0 = blockIdx.y * 128;
  const int mat = blockIdx.z;
  const float* W    = g_Wx + (size_t)mat*Hh*Ee;
  const float* bias = mat ? wxhB : wxcB;
  float* Cout = mat ? g_XH : g_XC;
  if (tid < 128) toks[tid] = tokens[m0 + tid];
  __syncthreads();
  const int lane = tid & 31, warp = tid >> 5;
  const int wm = (warp & 1) * 64, wn = (warp >> 1) * 32;
  const int g = lane >> 2, tg = lane & 3;

  float acc[4][4][4];
#pragma unroll
  for (int a=0;a<4;a++)
#pragma unroll
    for (int b=0;b<4;b++)
#pragma unroll
      for (int c=0;c<4;c++) acc[a][b][c]=0.f;

  auto load_tile = [&](int p, int kbi){
    int kb = kbi * 32;
#pragma unroll
    for (int i = 0; i < 4; i++){
      int idx = tid + i*256, row = idx>>3, c4 = (idx&7)*4;
      cpa16(&Ash[p*4608 + row*36 + c4], g_We + (size_t)toks[row]*Ee + kb + c4);
      cpa16(&Bsh[p*4608 + row*36 + c4], W + (size_t)(n0+row)*Ee + kb + c4);
    }
  };

#pragma unroll
  for (int p = 0; p < PIPE-1; p++){ load_tile(p, p); cpa_commit(); }
  for (int it = 0; it < 32; it++){
    cpa_wait<PIPE-2>();
    __syncthreads();
    int nx = it + PIPE - 1;
    if (nx < 32) load_tile(nx % PIPE, nx);
    cpa_commit();
    compute_64x32(Ash + (it%PIPE)*4608, Bsh + (it%PIPE)*4608, acc, wm, wn, g, tg);
  }

#pragma unroll
  for (int mi=0; mi<4; mi++){
    int r = m0 + wm + mi*16 + g;
#pragma unroll
    for (int ni=0; ni<4; ni++){
      int c = n0 + wn + ni*8 + 2*tg;
      float b0 = bias[c], b1 = bias[c+1];
      size_t o = (size_t)r*Hh + c;
      Cout[o]        = acc[mi][ni][0] + b0;
      Cout[o+1]      = acc[mi][ni][1] + b1;
      Cout[o+8*Hh]   = acc[mi][ni][2] + b0;
      Cout[o+8*Hh+1] = acc[mi][ni][3] + b1;
    }
  }
}

// ---------------- phase 2: persistent recurrence ----------------
// 128 CTAs = 2 mrow x 64 nt. CTA: rows [mrow*64,+64), cols [nt*16,+16), BOTH mats, K=1024.
// h carried in registers; fp16 twin double-buffered; mrow-local barriers.
// Next-stage B prefetch issued AFTER chunk-0 compute (off the stage-entry critical path).
__global__ void __launch_bounds__(256) rnn_kernel(float* __restrict__ outp)
{
  extern __shared__ unsigned char smraw[];
  __half* Aw = (__half*)smraw;               // 2 x 18432 halves
  __half* Bw = (__half*)smraw + 2*18432;     // 2 x 36864 halves
  const int tid = threadIdx.x;
  const int bid = blockIdx.x;
  const int lane = tid & 31, warp = tid >> 5;
  const int wm = (warp & 3) * 16;
  const int wn = (warp >> 2) * 8;
  const int wni = warp >> 2;
  const int g = lane >> 2, tg = lane & 3;
  const int mrow = bid >> 6;
  const int nt   = bid & 63;
  const int rbase = mrow * 64;
  const int n0 = nt * 16;
  const int r0 = rbase + wm + g, r1 = r0 + 8;
  const int c0 = n0 + wn + 2*tg;
  unsigned ep = 0;

  const unsigned sA = (unsigned)__cvta_generic_to_shared(Aw);
  const unsigned sB = (unsigned)__cvta_generic_to_shared(Bw);
  const int lj = lane >> 3, lr = lane & 7;
  const unsigned aoff = (unsigned)(((wm + lr + ((lj&1)<<3))*72 + ((lj>>1)<<3)) * 2);
  const unsigned boff = (unsigned)(((wn + lr)*72 + lj*8) * 2);

  auto load_A = [&](int par, int kb, int p){   // chunk kb (0..3): 64 rows x 256 k
    const __half* src = g_Hh2 + (size_t)par*Bb*Hh + (size_t)rbase*Hh;
#pragma unroll
    for (int i = 0; i < 8; i++){
      int idx = tid + i*256;
      int row = idx >> 5;
      int kh  = (idx & 31) * 8;
      int blk = kh >> 6, kk = kh & 63;
      cpa16(&Aw[p*18432 + blk*4608 + row*72 + kk],
            src + (size_t)row*Hh + kb*256 + kh);
    }
  };
  auto load_B = [&](int s, int q){
#pragma unroll
    for (int i = 0; i < 16; i++){
      int idx = tid + i*256;
      int m2 = idx >> 11;
      int j  = idx & 2047;
      int blk = j >> 7;
      int jj = j & 127;
      int row = jj >> 3, c8 = (jj & 7) * 8;
      const __half* W = (m2 ? g_Wh : g_Wc) + (size_t)s*Hh*Hh;
      cpa16(&Bw[q*36864 + m2*18432 + blk*1152 + row*72 + c8],
            W + (size_t)(n0+row)*Hh + blk*64 + c8);
    }
  };

  float hp0 = 0.f, hp1 = 0.f, hp2 = 0.f, hp3 = 0.f;

  load_B(0, 0); cpa_commit();
  {
    uint2 z; z.x = 0u; z.y = 0u;
    ((uint2*)g_Hh2)[bid*256 + tid] = z;        // buffer 0 zeros
  }
  gsyncg(ep, mrow, nt);

  for (int t = 0; t < Tt; t++){
    for (int s = 0; s < NBLK; s++){
      const int par = s & 1;
      const unsigned cbB = sB + (unsigned)(par*36864*2) + boff;
      const unsigned hbB = cbB + (unsigned)(18432*2);

      float accc[4] = {0.f,0.f,0.f,0.f};
      float acch[4] = {0.f,0.f,0.f,0.f};

      // issue A0, A1 only (B-next deferred past chunk-0 compute)
      load_A(par, 0, 0); cpa_commit();
      load_A(par, 1, 1); cpa_commit();

      // chunk 0 (needs A0 only)
      cpa_wait<1>(); __syncthreads();
#pragma unroll
      for (int b = 0; b < 4; b++)
        compute_blk_ldsm(sA + (unsigned)(0*18432 + b*4608)*2 + aoff,
                         cbB + (unsigned)((0*4+b)*1152)*2,
                         hbB + (unsigned)((0*4+b)*1152)*2, accc, acch);
      __syncthreads();
      load_A(par, 2, 0); cpa_commit();
      {
        int sn = s + 1; if (sn == NBLK) sn = 0;
        load_B(sn, par ^ 1); cpa_commit();
      }

      // chunk 1 (needs A1)
      cpa_wait<2>(); __syncthreads();
#pragma unroll
      for (int b = 0; b < 4; b++)
        compute_blk_ldsm(sA + (unsigned)(1*18432 + b*4608)*2 + aoff,
                         cbB + (unsigned)((1*4+b)*1152)*2,
                         hbB + (unsigned)((1*4+b)*1152)*2, accc, acch);
      __syncthreads();
      load_A(par, 3, 1); cpa_commit();

      // chunk 2 (needs A2)
      cpa_wait<2>(); __syncthreads();
#pragma unroll
      for (int b = 0; b < 4; b++)
        compute_blk_ldsm(sA + (unsigned)(0*18432 + b*4608)*2 + aoff,
                         cbB + (unsigned)((2*4+b)*1152)*2,
                         hbB + (unsigned)((2*4+b)*1152)*2, accc, acch);

      // chunk 3 (wait<0> covers A3 + next-stage B)
      cpa_wait<0>(); __syncthreads();
#pragma unroll
      for (int b = 0; b < 4; b++)
        compute_blk_ldsm(sA + (unsigned)(1*18432 + b*4608)*2 + aoff,
                         cbB + (unsigned)((3*4+b)*1152)*2,
                         hbB + (unsigned)((3*4+b)*1152)*2, accc, acch);

      // fused epilogue
      {
        const int np = par ^ 1;
        __half* Hh16 = g_Hh2 + (size_t)np*Bb*Hh;

        float sc0=accc[0], sc1=accc[1], sc2=accc[2], sc3=accc[3];
        float sh0=acch[0], sh1=acch[1], sh2=acch[2], sh3=acch[3];
        if (s == 0){
          const float* XCb = g_XC + ((size_t)t<<17);
          const float* XHb = g_XH + ((size_t)t<<17);
          float2 a0 = *(const float2*)(XCb + (size_t)r0*Hh + c0);
          float2 a1 = *(const float2*)(XCb + (size_t)r1*Hh + c0);
          float2 b0 = *(const float2*)(XHb + (size_t)r0*Hh + c0);
          float2 b1 = *(const float2*)(XHb + (size_t)r1*Hh + c0);
          sc0 += a0.x; sc1 += a0.y; sc2 += a1.x; sc3 += a1.y;
          sh0 += b0.x; sh1 += b0.y; sh2 += b1.x; sh3 += b1.y;
        }
        const bool use_tanh = (s == 0) || (s & 1);
        float g0 = sigm(sc0), g1 = sigm(sc1), g2 = sigm(sc2), g3 = sigm(sc3);
        float a0 = use_tanh ? tanhf(sh0) : fmaxf(sh0, 0.f);
        float a1 = use_tanh ? tanhf(sh1) : fmaxf(sh1, 0.f);
        float a2 = use_tanh ? tanhf(sh2) : fmaxf(sh2, 0.f);
        float a3 = use_tanh ? tanhf(sh3) : fmaxf(sh3, 0.f);
        float n0v = g0*a0 + (1.f-g0)*hp0;
        float n1v = g1*a1 + (1.f-g1)*hp1;
        float n2v = g2*a2 + (1.f-g2)*hp2;
        float n3v = g3*a3 + (1.f-g3)*hp3;

        if (s < NBLK-1){
          hp0 = n0v; hp1 = n1v; hp2 = n2v; hp3 = n3v;
          __half2 p0 = __floats2half2_rn(n0v, n1v);
          __half2 p1 = __floats2half2_rn(n2v, n3v);
          *(unsigned*)(Hh16 + (size_t)r0*Hh + c0) = *(unsigned*)&p0;
          *(unsigned*)(Hh16 + (size_t)r1*Hh + c0) = *(unsigned*)&p1;
        } else {
          float* Ob = g_OUT + ((size_t)t<<17);
          *(float2*)(Ob + (size_t)r0*Hh + c0) = make_float2(rndtf(n0v), rndtf(n1v));
          *(float2*)(Ob + (size_t)r1*Hh + c0) = make_float2(rndtf(n2v), rndtf(n3v));
          float ss0 = n0v*n0v + n1v*n1v;
          float ss1 = n2v*n2v + n3v*n3v;
          ss0 += __shfl_xor_sync(0xffffffffu, ss0, 1);
          ss0 += __shfl_xor_sync(0xffffffffu, ss0, 2);
          ss1 += __shfl_xor_sync(0xffffffffu, ss1, 1);
          ss1 += __shfl_xor_sync(0xffffffffu, ss1, 2);
          if (tg == 0){
            g_pss[r0*128 + nt*2 + wni] = ss0;
            g_pss[r1*128 + nt*2 + wni] = ss1;
          }
          gsyncg(ep, mrow, nt);
          float t0 = 0.f, t1 = 0.f;
          const float4* q0 = (const float4*)(g_pss + (size_t)r0*128);
          const float4* q1 = (const float4*)(g_pss + (size_t)r1*128);
#pragma unroll
          for (int j = 0; j < 32; j++){
            float4 v = q0[j]; t0 += v.x + v.y + v.z + v.w;
            float4 w = q1[j]; t1 += w.x + w.y + w.z + w.w;
          }
          float nm0 = sqrtf(t0), nm1 = sqrtf(t1);
          float sA0 = (nm0 > 25.f) ? (25.f / nm0) : 1.f;
          float sA1 = (nm1 > 25.f) ? (25.f / nm1) : 1.f;
          hp0 = n0v * sA0; hp1 = n1v * sA0;
          hp2 = n2v * sA1; hp3 = n3v * sA1;
          __half2 p0 = __floats2half2_rn(hp0, hp1);
          __half2 p1 = __floats2half2_rn(hp2, hp3);
          *(unsigned*)(Hh16 + (size_t)r0*Hh + c0) = *(unsigned*)&p0;
          *(unsigned*)(Hh16 + (size_t)r1*Hh + c0) = *(unsigned*)&p1;
        }
      }
      gsyncg(ep, mrow, nt);
    }
  }

  // hT (clipped final hidden, from registers)
  {
    float* o = outp + (size_t)Tt*Bb*Vv;
    *(float2*)(o + (size_t)r0*Hh + c0) = make_float2(hp0, hp1);
    *(float2*)(o + (size_t)r1*Hh + c0) = make_float2(hp2, hp3);
  }
}

// ---------------- phase 3: decoder GEMM (tf32) ----------------
__global__ void __launch_bounds__(256, 2) dec_kernel(
  const float* __restrict__ decB, float* __restrict__ outp)
{
  extern __shared__ unsigned char smraw[];
  float* Ash = (float*)smraw;
  float* Bsh = (float*)smraw + PIPE*4608;
  const int tid = threadIdx.x;
  const int n0 = blockIdx.x * 128;
  const int m0 = blockIdx.y * 128;
  const int lane = tid & 31, warp = tid >> 5;
  const int wm = (warp & 1) * 64, wn = (warp >> 1) * 32;
  const int g = lane >> 2, tg = lane & 3;
  float acc[4][4][4];
#pragma unroll
  for (int a=0;a<4;a++)
#pragma unroll
    for (int b=0;b<4;b++)
#pragma unroll
      for (int c=0;c<4;c++) acc[a][b][c]=0.f;

  auto load_tile = [&](int p, int kbi){
    int kb = kbi * 32;
#pragma unroll
    for (int i = 0; i < 4; i++){
      int idx = tid + i*256, row = idx>>3, c4 = (idx&7)*4;
      cpa16(&Ash[p*4608 + row*36 + c4], g_OUT + (size_t)(m0+row)*Hh + kb + c4);
      cpa16(&Bsh[p*4608 + row*36 + c4], g_Wd + (size_t)(n0+row)*Hh + kb + c4);
    }
  };

#pragma unroll
  for (int p = 0; p < PIPE-1; p++){ load_tile(p, p); cpa_commit(); }
  for (int it = 0; it < 32; it++){
    cpa_wait<PIPE-2>();
    __syncthreads();
    int nx = it + PIPE - 1;
    if (nx < 32) load_tile(nx % PIPE, nx);
    cpa_commit();
    compute_64x32(Ash + (it%PIPE)*4608, Bsh + (it%PIPE)*4608, acc, wm, wn, g, tg);
  }

#pragma unroll
  for (int mi=0;mi<4;mi++){
    int r = m0 + wm + mi*16 + g;
#pragma unroll
    for (int ni=0;ni<4;ni++){
      int c = n0 + wn + ni*8 + 2*tg;
      if (c < Vv){
        float b0 = decB[c], b1 = decB[c+1];
        size_t o  = (size_t)r*Vv + c;
        size_t o2 = o + (size_t)8*Vv;
        outp[o]    = acc[mi][ni][0] + b0;
        outp[o+1]  = acc[mi][ni][1] + b1;
        outp[o2]   = acc[mi][ni][2] + b0;
        outp[o2+1] = acc[mi][ni][3] + b1;
      }
    }
  }
}

// ---------------- launch ----------------
extern "C" void kernel_launch(void* const* d_in, const int* in_sizes, int n_in,
                              void* d_out, int out_size){
  const int*   tokens = (const int*)  d_in[0];
  const float* embW   = (const float*)d_in[1];
  const float* wxcW   = (const float*)d_in[2];
  const float* wxcB   = (const float*)d_in[3];
  const float* wxhW   = (const float*)d_in[4];
  const float* wxhB   = (const float*)d_in[5];
  const float* w_hc   = (const float*)d_in[6];
  const float* w_hh   = (const float*)d_in[7];
  const float* edge_h = (const float*)d_in[8];
  const float* edge_c = (const float*)d_in[9];
  const float* decW   = (const float*)d_in[10];
  const float* decB   = (const float*)d_in[11];
  float* outp = (float*)d_out;
  (void)in_sizes; (void)n_in; (void)out_size;

  const int RNN_SMEM  = (2*18432 + 2*36864) * 2;   // 221184 B
  const int GEMM_SMEM = PIPE * 2 * 4608 * 4;       // 73728 B
  cudaFuncSetAttribute(xproj_kernel, cudaFuncAttributeMaxDynamicSharedMemorySize, GEMM_SMEM);
  cudaFuncSetAttribute(rnn_kernel,   cudaFuncAttributeMaxDynamicSharedMemorySize, RNN_SMEM);
  cudaFuncSetAttribute(dec_kernel,   cudaFuncAttributeMaxDynamicSharedMemorySize, GEMM_SMEM);

  // reset barrier flags
  void *pArr = nullptr, *pRel = nullptr;
  cudaGetSymbolAddress(&pArr, g_arr);
  cudaGetSymbolAddress(&pRel, g_rel2);
  cudaMemsetAsync(pArr, 0, sizeof(unsigned)*GRID_R);
  cudaMemsetAsync(pRel, 0, sizeof(unsigned)*2);

  const long PREP_TOTAL = S_WC + S_WH + S_WE + S_WX + S_WD;
  prep_all<<<(unsigned)((PREP_TOTAL + 255) / 256), 256>>>(
      w_hc, edge_c, w_hh, edge_h, embW, wxcW, wxhW, decW);

  xproj_kernel<<<dim3(8, 64, 2), 256, GEMM_SMEM>>>(tokens, wxcB, wxhB);
  rnn_kernel<<<GRID_R, 256, RNN_SMEM>>>(outp);
  dec_kernel<<<dim3(VPAD/128, 64), 256, GEMM_SMEM>>>(decB, outp);
}

// round 17
// speedup vs baseline: 1.2164x; 1.0127x over previous
#include <cuda_runtime.h>
#include <cuda_fp16.h>
#include <math.h>

#define Tt   64
#define Bb   128
#define Ee   1024
#define Hh   1024
#define Vv   10000
#define NBLK 12
#define GRID_R 128
#define VPAD 10112
#define PIPE 2

// ---------------- scratch (device globals) ----------------
__device__ __align__(16) float  g_XC[Tt*Bb*Hh];
__device__ __align__(16) float  g_XH[Tt*Bb*Hh];
__device__ __align__(16) float  g_OUT[Tt*Bb*Hh];    // tf32-rounded pre-clip hidden (decoder A)
__device__ __align__(16) __half g_Hh2[2*Bb*Hh];     // fp16 hidden, stage-parity double buffer
__device__ __align__(16) float  g_pss[Bb*128];      // per-(row, nt*2+wni) norm partials
__device__ __align__(16) __half g_Wc[NBLK*Hh*Hh];   // fp16 [w_hc, edge_c x11]  (gate)
__device__ __align__(16) __half g_Wh[NBLK*Hh*Hh];   // fp16 [w_hh, edge_h x11]  (candidate)
__device__ __align__(16) __half g_Weh[Vv*Ee];       // fp16 embedding (xproj A)
__device__ __align__(16) __half g_Wxh[2*Hh*Ee];     // fp16 wxc, wxh (xproj B)
__device__ __align__(16) float  g_Wd[VPAD*Hh];      // tf32 + zero-padded dec_W
__device__ unsigned g_arr[GRID_R];
__device__ unsigned g_rel2[2];

// ---------------- helpers ----------------
__device__ __forceinline__ unsigned f2tf32(float x){
  unsigned u; asm("cvt.rna.tf32.f32 %0, %1;" : "=r"(u) : "f"(x)); return u;
}
__device__ __forceinline__ float rndtf(float x){ return __uint_as_float(f2tf32(x)); }

__device__ __forceinline__ uint2 pack4h(float4 v){
  __half2 a = __floats2half2_rn(v.x, v.y);
  __half2 b = __floats2half2_rn(v.z, v.w);
  uint2 u;
  u.x = *(unsigned*)&a;
  u.y = *(unsigned*)&b;
  return u;
}

__device__ __forceinline__ void mma_tf32(float* c, const unsigned* a, const unsigned* b){
  asm volatile(
    "mma.sync.aligned.m16n8k8.row.col.f32.tf32.tf32.f32 "
    "{%0,%1,%2,%3}, {%4,%5,%6,%7}, {%8,%9}, {%0,%1,%2,%3};\n"
    : "+f"(c[0]), "+f"(c[1]), "+f"(c[2]), "+f"(c[3])
    : "r"(a[0]), "r"(a[1]), "r"(a[2]), "r"(a[3]), "r"(b[0]), "r"(b[1]));
}

__device__ __forceinline__ void mma_fp16(float* c, const unsigned* a, const unsigned* b){
  asm volatile(
    "mma.sync.aligned.m16n8k16.row.col.f32.f16.f16.f32 "
    "{%0,%1,%2,%3}, {%4,%5,%6,%7}, {%8,%9}, {%0,%1,%2,%3};\n"
    : "+f"(c[0]), "+f"(c[1]), "+f"(c[2]), "+f"(c[3])
    : "r"(a[0]), "r"(a[1]), "r"(a[2]), "r"(a[3]), "r"(b[0]), "r"(b[1]));
}

__device__ __forceinline__ void ldsm4(unsigned* r, unsigned a){
  asm volatile("ldmatrix.sync.aligned.m8n8.x4.shared.b16 {%0,%1,%2,%3}, [%4];"
    : "=r"(r[0]), "=r"(r[1]), "=r"(r[2]), "=r"(r[3]) : "r"(a));
}

__device__ __forceinline__ void cpa16(void* smemp, const void* gmem){
  unsigned s = (unsigned)__cvta_generic_to_shared(smemp);
  asm volatile("cp.async.cg.shared.global [%0], [%1], 16;\n" :: "r"(s), "l"(gmem));
}
__device__ __forceinline__ void cpa_commit(){ asm volatile("cp.async.commit_group;\n"); }
template<int N> __device__ __forceinline__ void cpa_wait(){
  asm volatile("cp.async.wait_group %0;\n" :: "n"(N));
}

__device__ __forceinline__ float sigm(float x){ return 1.f/(1.f + expf(-x)); }

// group barrier: 64 CTAs of the same mrow (recurrence is row-independent).
__device__ __forceinline__ void gsyncg(unsigned &ep, int mrow, int lid){
  ep++;
  __syncthreads();
  if (lid == 0){
    if (threadIdx.x > 0 && threadIdx.x < 64){
      while (*(volatile unsigned*)&g_arr[mrow*64 + threadIdx.x] < ep) { }
    }
    __syncthreads();
    if (threadIdx.x == 0){ __threadfence(); *(volatile unsigned*)&g_rel2[mrow] = ep; }
  } else {
    if (threadIdx.x == 0){
      __threadfence();
      *(volatile unsigned*)&g_arr[mrow*64 + lid] = ep;
      while (*(volatile unsigned*)&g_rel2[mrow] < ep) { }
    }
  }
  __syncthreads();
  __threadfence();
}

// tf32 warp tile 64x32 (mi4 x ni4), k-block 32 floats, smem row stride 36 u32
__device__ __forceinline__ void compute_64x32(const float* Af, const float* Bf,
      float acc[4][4][4], int wm, int wn, int g, int tg){
  const unsigned* As = (const unsigned*)Af;
  const unsigned* Bs = (const unsigned*)Bf;
#pragma unroll
  for (int ks = 0; ks < 32; ks += 8){
    unsigned a[4][4], b[4][2];
#pragma unroll
    for (int mi = 0; mi < 4; mi++){
      int r = wm + mi*16 + g;
      a[mi][0] = As[r*36 + ks+tg];
      a[mi][1] = As[(r+8)*36 + ks+tg];
      a[mi][2] = As[r*36 + ks+tg+4];
      a[mi][3] = As[(r+8)*36 + ks+tg+4];
    }
#pragma unroll
    for (int ni = 0; ni < 4; ni++){
      int rr = wn + ni*8 + g;
      b[ni][0] = Bs[rr*36 + ks+tg];
      b[ni][1] = Bs[rr*36 + ks+tg+4];
    }
#pragma unroll
    for (int mi = 0; mi < 4; mi++)
#pragma unroll
      for (int ni = 0; ni < 4; ni++)
        mma_tf32(acc[mi][ni], a[mi], b[ni]);
  }
}

// fp16 warp tile 64x32 (mi4 x ni4), k-block 64 halves, smem row stride 72 halves
__device__ __forceinline__ void compute_64x32h(const __half* Ah, const __half* Bh,
      float acc[4][4][4], int wm, int wn, int g, int tg){
  const unsigned* As = (const unsigned*)Ah;
  const unsigned* Bs = (const unsigned*)Bh;
#pragma unroll
  for (int ks = 0; ks < 64; ks += 16){
    int ko = ks/2 + tg;
    unsigned a[4][4], b[4][2];
#pragma unroll
    for (int mi = 0; mi < 4; mi++){
      int r = wm + mi*16 + g;
      a[mi][0] = As[r*36 + ko];
      a[mi][1] = As[(r+8)*36 + ko];
      a[mi][2] = As[r*36 + ko + 4];
      a[mi][3] = As[(r+8)*36 + ko + 4];
    }
#pragma unroll
    for (int ni = 0; ni < 4; ni++){
      int rr = wn + ni*8 + g;
      b[ni][0] = Bs[rr*36 + ko];
      b[ni][1] = Bs[rr*36 + ko + 4];
    }
#pragma unroll
    for (int mi = 0; mi < 4; mi++)
#pragma unroll
      for (int ni = 0; ni < 4; ni++)
        mma_fp16(acc[mi][ni], a[mi], b[ni]);
  }
}

// fp16: one 64-k block via ldmatrix, warp tile 16(M)x8(N), both mats share A fragments.
__device__ __forceinline__ void compute_blk_ldsm(unsigned abase, unsigned cbase, unsigned hbase,
      float accc[4], float acch[4]){
  unsigned a[4][4];
#pragma unroll
  for (int ks = 0; ks < 4; ks++) ldsm4(a[ks], abase + ks*32);
  unsigned qc[2][4], qh[2][4];
  ldsm4(qc[0], cbase);
  ldsm4(qc[1], cbase + 64);
  ldsm4(qh[0], hbase);
  ldsm4(qh[1], hbase + 64);
#pragma unroll
  for (int ks = 0; ks < 4; ks++){
    mma_fp16(accc, a[ks], &qc[ks>>1][(ks&1)*2]);
    mma_fp16(acch, a[ks], &qh[ks>>1][(ks&1)*2]);
  }
}

// ---------------- prep: wc/wh/we/wx -> fp16, wd -> tf32 ----------------
#define S_WC  3145728L
#define S_WH  3145728L
#define S_WE  2560000L
#define S_WX   524288L
#define S_WD  2588672L
__global__ void __launch_bounds__(256) prep_all(
    const float* __restrict__ w_hc, const float* __restrict__ edge_c,
    const float* __restrict__ w_hh, const float* __restrict__ edge_h,
    const float* __restrict__ embW, const float* __restrict__ wxcW,
    const float* __restrict__ wxhW, const float* __restrict__ decW)
{
  long i = (long)blockIdx.x*256 + threadIdx.x;
  const long F4 = (long)Hh*Hh/4;
  if (i < S_WC){
    float4 v = (i < F4) ? ((const float4*)w_hc)[i] : ((const float4*)edge_c)[i-F4];
    ((uint2*)g_Wc)[i] = pack4h(v);
    return;
  }
  if ((i -= S_WC) < S_WH){
    float4 v = (i < F4) ? ((const float4*)w_hh)[i] : ((const float4*)edge_h)[i-F4];
    ((uint2*)g_Wh)[i] = pack4h(v);
    return;
  }
  if ((i -= S_WH) < S_WE){
    float4 v = ((const float4*)embW)[i];
    ((uint2*)g_Weh)[i] = pack4h(v);
    return;
  }
  if ((i -= S_WE) < S_WX){
    const long G4 = (long)Hh*Ee/4;
    float4 v = (i < G4) ? ((const float4*)wxcW)[i] : ((const float4*)wxhW)[i-G4];
    ((uint2*)g_Wxh)[i] = pack4h(v);
    return;
  }
  if ((i -= S_WX) < S_WD){
    long row = (i*4) >> 10;
    float4 v = (row < Vv) ? ((const float4*)decW)[i] : make_float4(0.f,0.f,0.f,0.f);
    float4 r; r.x=rndtf(v.x); r.y=rndtf(v.y); r.z=rndtf(v.z); r.w=rndtf(v.w);
    ((float4*)g_Wd)[i] = r;
  }
}

// ---------------- phase 1: input projections (fp16 mma) ----------------
__global__ void __launch_bounds__(256) xproj_kernel(
    const int* __restrict__ tokens,
    const float* __restrict__ wxcB, const float* __restrict__ wxhB)
{
  extern __shared__ unsigned char smraw[];
  __half* Ash = (__half*)smraw;               // PIPE * 128*72 halves
  __half* Bsh = (__half*)smraw + PIPE*9216;   // PIPE * 128*72 halves
  __shared__ int toks[128];
  const int tid = threadIdx.x;
  const int n0 = blockIdx.x * 128;
  const int m0 = blockIdx.y * 128;
  const int mat = blockIdx.z;
  const __half* W   = g_Wxh + (size_t)mat*Hh*Ee;
  const float* bias = mat ? wxhB : wxcB;
  float* Cout = mat ? g_XH : g_XC;
  if (tid < 128) toks[tid] = tokens[m0 + tid];
  __syncthreads();
  const int lane = tid & 31, warp = tid >> 5;
  const int wm = (warp & 1) * 64, wn = (warp >> 1) * 32;
  const int g = lane >> 2, tg = lane & 3;

  float acc[4][4][4];
#pragma unroll
  for (int a=0;a<4;a++)
#pragma unroll
    for (int b=0;b<4;b++)
#pragma unroll
      for (int c=0;c<4;c++) acc[a][b][c]=0.f;

  auto load_tile = [&](int p, int kbi){
    int kb = kbi * 64;
#pragma unroll
    for (int i = 0; i < 4; i++){
      int idx = tid + i*256, row = idx>>3, c8 = (idx&7)*8;
      cpa16(&Ash[p*9216 + row*72 + c8], g_Weh + (size_t)toks[row]*Ee + kb + c8);
      cpa16(&Bsh[p*9216 + row*72 + c8], W + (size_t)(n0+row)*Ee + kb + c8);
    }
  };

#pragma unroll
  for (int p = 0; p < PIPE-1; p++){ load_tile(p, p); cpa_commit(); }
  for (int it = 0; it < 16; it++){
    cpa_wait<PIPE-2>();
    __syncthreads();
    int nx = it + PIPE - 1;
    if (nx < 16) load_tile(nx % PIPE, nx);
    cpa_commit();
    compute_64x32h(Ash + (it%PIPE)*9216, Bsh + (it%PIPE)*9216, acc, wm, wn, g, tg);
  }

#pragma unroll
  for (int mi=0; mi<4; mi++){
    int r = m0 + wm + mi*16 + g;
#pragma unroll
    for (int ni=0; ni<4; ni++){
      int c = n0 + wn + ni*8 + 2*tg;
      float b0 = bias[c], b1 = bias[c+1];
      size_t o = (size_t)r*Hh + c;
      Cout[o]        = acc[mi][ni][0] + b0;
      Cout[o+1]      = acc[mi][ni][1] + b1;
      Cout[o+8*Hh]   = acc[mi][ni][2] + b0;
      Cout[o+8*Hh+1] = acc[mi][ni][3] + b1;
    }
  }
}

// ---------------- phase 2: persistent recurrence (r14 layout, verbatim) ----------------
// 128 CTAs = 2 mrow x 64 nt. CTA: rows [mrow*64,+64), cols [nt*16,+16), BOTH mats, K=1024.
__global__ void __launch_bounds__(256) rnn_kernel(float* __restrict__ outp)
{
  extern __shared__ unsigned char smraw[];
  __half* Aw = (__half*)smraw;               // 2 x 18432 halves
  __half* Bw = (__half*)smraw + 2*18432;     // 2 x 36864 halves
  const int tid = threadIdx.x;
  const int bid = blockIdx.x;
  const int lane = tid & 31, warp = tid >> 5;
  const int wm = (warp & 3) * 16;
  const int wn = (warp >> 2) * 8;
  const int wni = warp >> 2;
  const int g = lane >> 2, tg = lane & 3;
  const int mrow = bid >> 6;
  const int nt   = bid & 63;
  const int rbase = mrow * 64;
  const int n0 = nt * 16;
  const int r0 = rbase + wm + g, r1 = r0 + 8;
  const int c0 = n0 + wn + 2*tg;
  unsigned ep = 0;

  const unsigned sA = (unsigned)__cvta_generic_to_shared(Aw);
  const unsigned sB = (unsigned)__cvta_generic_to_shared(Bw);
  const int lj = lane >> 3, lr = lane & 7;
  const unsigned aoff = (unsigned)(((wm + lr + ((lj&1)<<3))*72 + ((lj>>1)<<3)) * 2);
  const unsigned boff = (unsigned)(((wn + lr)*72 + lj*8) * 2);

  auto load_A = [&](int par, int kb, int p){
    const __half* src = g_Hh2 + (size_t)par*Bb*Hh + (size_t)rbase*Hh;
#pragma unroll
    for (int i = 0; i < 8; i++){
      int idx = tid + i*256;
      int row = idx >> 5;
      int kh  = (idx & 31) * 8;
      int blk = kh >> 6, kk = kh & 63;
      cpa16(&Aw[p*18432 + blk*4608 + row*72 + kk],
            src + (size_t)row*Hh + kb*256 + kh);
    }
  };
  auto load_B = [&](int s, int q){
#pragma unroll
    for (int i = 0; i < 16; i++){
      int idx = tid + i*256;
      int m2 = idx >> 11;
      int j  = idx & 2047;
      int blk = j >> 7;
      int jj = j & 127;
      int row = jj >> 3, c8 = (jj & 7) * 8;
      const __half* W = (m2 ? g_Wh : g_Wc) + (size_t)s*Hh*Hh;
      cpa16(&Bw[q*36864 + m2*18432 + blk*1152 + row*72 + c8],
            W + (size_t)(n0+row)*Hh + blk*64 + c8);
    }
  };

  float hp0 = 0.f, hp1 = 0.f, hp2 = 0.f, hp3 = 0.f;

  load_B(0, 0); cpa_commit();
  {
    uint2 z; z.x = 0u; z.y = 0u;
    ((uint2*)g_Hh2)[bid*256 + tid] = z;
  }
  gsyncg(ep, mrow, nt);

  for (int t = 0; t < Tt; t++){
    for (int s = 0; s < NBLK; s++){
      const int par = s & 1;
      const unsigned cbB = sB + (unsigned)(par*36864*2) + boff;
      const unsigned hbB = cbB + (unsigned)(18432*2);

      float accc[4] = {0.f,0.f,0.f,0.f};
      float acch[4] = {0.f,0.f,0.f,0.f};

      load_A(par, 0, 0); cpa_commit();
      load_A(par, 1, 1); cpa_commit();
      {
        int sn = s + 1; if (sn == NBLK) sn = 0;
        load_B(sn, par ^ 1); cpa_commit();
      }

      // chunk 0
      cpa_wait<2>(); __syncthreads();
#pragma unroll
      for (int b = 0; b < 4; b++)
        compute_blk_ldsm(sA + (unsigned)(0*18432 + b*4608)*2 + aoff,
                         cbB + (unsigned)((0*4+b)*1152)*2,
                         hbB + (unsigned)((0*4+b)*1152)*2, accc, acch);
      __syncthreads();
      load_A(par, 2, 0); cpa_commit();

      // chunk 1
      cpa_wait<2>(); __syncthreads();
#pragma unroll
      for (int b = 0; b < 4; b++)
        compute_blk_ldsm(sA + (unsigned)(1*18432 + b*4608)*2 + aoff,
                         cbB + (unsigned)((1*4+b)*1152)*2,
                         hbB + (unsigned)((1*4+b)*1152)*2, accc, acch);
      __syncthreads();
      load_A(par, 3, 1); cpa_commit();

      // chunk 2
      cpa_wait<1>(); __syncthreads();
#pragma unroll
      for (int b = 0; b < 4; b++)
        compute_blk_ldsm(sA + (unsigned)(0*18432 + b*4608)*2 + aoff,
                         cbB + (unsigned)((2*4+b)*1152)*2,
                         hbB + (unsigned)((2*4+b)*1152)*2, accc, acch);

      // chunk 3 (wait<0> also covers next-stage B)
      cpa_wait<0>(); __syncthreads();
#pragma unroll
      for (int b = 0; b < 4; b++)
        compute_blk_ldsm(sA + (unsigned)(1*18432 + b*4608)*2 + aoff,
                         cbB + (unsigned)((3*4+b)*1152)*2,
                         hbB + (unsigned)((3*4+b)*1152)*2, accc, acch);

      // fused epilogue
      {
        const int np = par ^ 1;
        __half* Hh16 = g_Hh2 + (size_t)np*Bb*Hh;

        float sc0=accc[0], sc1=accc[1], sc2=accc[2], sc3=accc[3];
        float sh0=acch[0], sh1=acch[1], sh2=acch[2], sh3=acch[3];
        if (s == 0){
          const float* XCb = g_XC + ((size_t)t<<17);
          const float* XHb = g_XH + ((size_t)t<<17);
          float2 a0 = *(const float2*)(XCb + (size_t)r0*Hh + c0);
          float2 a1 = *(const float2*)(XCb + (size_t)r1*Hh + c0);
          float2 b0 = *(const float2*)(XHb + (size_t)r0*Hh + c0);
          float2 b1 = *(const float2*)(XHb + (size_t)r1*Hh + c0);
          sc0 += a0.x; sc1 += a0.y; sc2 += a1.x; sc3 += a1.y;
          sh0 += b0.x; sh1 += b0.y; sh2 += b1.x; sh3 += b1.y;
        }
        const bool use_tanh = (s == 0) || (s & 1);
        float g0 = sigm(sc0), g1 = sigm(sc1), g2 = sigm(sc2), g3 = sigm(sc3);
        float a0 = use_tanh ? tanhf(sh0) : fmaxf(sh0, 0.f);
        float a1 = use_tanh ? tanhf(sh1) : fmaxf(sh1, 0.f);
        float a2 = use_tanh ? tanhf(sh2) : fmaxf(sh2, 0.f);
        float a3 = use_tanh ? tanhf(sh3) : fmaxf(sh3, 0.f);
        float n0v = g0*a0 + (1.f-g0)*hp0;
        float n1v = g1*a1 + (1.f-g1)*hp1;
        float n2v = g2*a2 + (1.f-g2)*hp2;
        float n3v = g3*a3 + (1.f-g3)*hp3;

        if (s < NBLK-1){
          hp0 = n0v; hp1 = n1v; hp2 = n2v; hp3 = n3v;
          __half2 p0 = __floats2half2_rn(n0v, n1v);
          __half2 p1 = __floats2half2_rn(n2v, n3v);
          *(unsigned*)(Hh16 + (size_t)r0*Hh + c0) = *(unsigned*)&p0;
          *(unsigned*)(Hh16 + (size_t)r1*Hh + c0) = *(unsigned*)&p1;
        } else {
          float* Ob = g_OUT + ((size_t)t<<17);
          *(float2*)(Ob + (size_t)r0*Hh + c0) = make_float2(rndtf(n0v), rndtf(n1v));
          *(float2*)(Ob + (size_t)r1*Hh + c0) = make_float2(rndtf(n2v), rndtf(n3v));
          float ss0 = n0v*n0v + n1v*n1v;
          float ss1 = n2v*n2v + n3v*n3v;
          ss0 += __shfl_xor_sync(0xffffffffu, ss0, 1);
          ss0 += __shfl_xor_sync(0xffffffffu, ss0, 2);
          ss1 += __shfl_xor_sync(0xffffffffu, ss1, 1);
          ss1 += __shfl_xor_sync(0xffffffffu, ss1, 2);
          if (tg == 0){
            g_pss[r0*128 + nt*2 + wni] = ss0;
            g_pss[r1*128 + nt*2 + wni] = ss1;
          }
          gsyncg(ep, mrow, nt);
          float t0 = 0.f, t1 = 0.f;
          const float4* q0 = (const float4*)(g_pss + (size_t)r0*128);
          const float4* q1 = (const float4*)(g_pss + (size_t)r1*128);
#pragma unroll
          for (int j = 0; j < 32; j++){
            float4 v = q0[j]; t0 += v.x + v.y + v.z + v.w;
            float4 w = q1[j]; t1 += w.x + w.y + w.z + w.w;
          }
          float nm0 = sqrtf(t0), nm1 = sqrtf(t1);
          float sA0 = (nm0 > 25.f) ? (25.f / nm0) : 1.f;
          float sA1 = (nm1 > 25.f) ? (25.f / nm1) : 1.f;
          hp0 = n0v * sA0; hp1 = n1v * sA0;
          hp2 = n2v * sA1; hp3 = n3v * sA1;
          __half2 p0 = __floats2half2_rn(hp0, hp1);
          __half2 p1 = __floats2half2_rn(hp2, hp3);
          *(unsigned*)(Hh16 + (size_t)r0*Hh + c0) = *(unsigned*)&p0;
          *(unsigned*)(Hh16 + (size_t)r1*Hh + c0) = *(unsigned*)&p1;
        }
      }
      gsyncg(ep, mrow, nt);
    }
  }

  // hT (clipped final hidden, from registers)
  {
    float* o = outp + (size_t)Tt*Bb*Vv;
    *(float2*)(o + (size_t)r0*Hh + c0) = make_float2(hp0, hp1);
    *(float2*)(o + (size_t)r1*Hh + c0) = make_float2(hp2, hp3);
  }
}

// ---------------- phase 3: decoder GEMM (tf32) ----------------
__global__ void __launch_bounds__(256) dec_kernel(
  const float* __restrict__ decB, float* __restrict__ outp)
{
  extern __shared__ unsigned char smraw[];
  float* Ash = (float*)smraw;
  float* Bsh = (float*)smraw + PIPE*4608;
  const int tid = threadIdx.x;
  const int n0 = blockIdx.x * 128;
  const int m0 = blockIdx.y * 128;
  const int lane = tid & 31, warp = tid >> 5;
  const int wm = (warp & 1) * 64, wn = (warp >> 1) * 32;
  const int g = lane >> 2, tg = lane & 3;
  float acc[4][4][4];
#pragma unroll
  for (int a=0;a<4;a++)
#pragma unroll
    for (int b=0;b<4;b++)
#pragma unroll
      for (int c=0;c<4;c++) acc[a][b][c]=0.f;

  auto load_tile = [&](int p, int kbi){
    int kb = kbi * 32;
#pragma unroll
    for (int i = 0; i < 4; i++){
      int idx = tid + i*256, row = idx>>3, c4 = (idx&7)*4;
      cpa16(&Ash[p*4608 + row*36 + c4], g_OUT + (size_t)(m0+row)*Hh + kb + c4);
      cpa16(&Bsh[p*4608 + row*36 + c4], g_Wd + (size_t)(n0+row)*Hh + kb + c4);
    }
  };

#pragma unroll
  for (int p = 0; p < PIPE-1; p++){ load_tile(p, p); cpa_commit(); }
  for (int it = 0; it < 32; it++){
    cpa_wait<PIPE-2>();
    __syncthreads();
    int nx = it + PIPE - 1;
    if (nx < 32) load_tile(nx % PIPE, nx);
    cpa_commit();
    compute_64x32(Ash + (it%PIPE)*4608, Bsh + (it%PIPE)*4608, acc, wm, wn, g, tg);
  }

#pragma unroll
  for (int mi=0;mi<4;mi++){
    int r = m0 + wm + mi*16 + g;
#pragma unroll
    for (int ni=0;ni<4;ni++){
      int c = n0 + wn + ni*8 + 2*tg;
      if (c < Vv){
        float b0 = decB[c], b1 = decB[c+1];
        size_t o  = (size_t)r*Vv + c;
        size_t o2 = o + (size_t)8*Vv;
        outp[o]    = acc[mi][ni][0] + b0;
        outp[o+1]  = acc[mi][ni][1] + b1;
        outp[o2]   = acc[mi][ni][2] + b0;
        outp[o2+1] = acc[mi][ni][3] + b1;
      }
    }
  }
}

// ---------------- launch ----------------
extern "C" void kernel_launch(void* const* d_in, const int* in_sizes, int n_in,
                              void* d_out, int out_size){
  const int*   tokens = (const int*)  d_in[0];
  const float* embW   = (const float*)d_in[1];
  const float* wxcW   = (const float*)d_in[2];
  const float* wxcB   = (const float*)d_in[3];
  const float* wxhW   = (const float*)d_in[4];
  const float* wxhB   = (const float*)d_in[5];
  const float* w_hc   = (const float*)d_in[6];
  const float* w_hh   = (const float*)d_in[7];
  const float* edge_h = (const float*)d_in[8];
  const float* edge_c = (const float*)d_in[9];
  const float* decW   = (const float*)d_in[10];
  const float* decB   = (const float*)d_in[11];
  float* outp = (float*)d_out;
  (void)in_sizes; (void)n_in; (void)out_size;

  const int RNN_SMEM   = (2*18432 + 2*36864) * 2;   // 221184 B
  const int XPROJ_SMEM = PIPE * 2 * 9216 * 2;       // 73728 B (halves)
  const int DEC_SMEM   = PIPE * 2 * 4608 * 4;       // 73728 B (floats)
  cudaFuncSetAttribute(xproj_kernel, cudaFuncAttributeMaxDynamicSharedMemorySize, XPROJ_SMEM);
  cudaFuncSetAttribute(rnn_kernel,   cudaFuncAttributeMaxDynamicSharedMemorySize, RNN_SMEM);
  cudaFuncSetAttribute(dec_kernel,   cudaFuncAttributeMaxDynamicSharedMemorySize, DEC_SMEM);

  // reset barrier flags
  void *pArr = nullptr, *pRel = nullptr;
  cudaGetSymbolAddress(&pArr, g_arr);
  cudaGetSymbolAddress(&pRel, g_rel2);
  cudaMemsetAsync(pArr, 0, sizeof(unsigned)*GRID_R);
  cudaMemsetAsync(pRel, 0, sizeof(unsigned)*2);

  const long PREP_TOTAL = S_WC + S_WH + S_WE + S_WX + S_WD;
  prep_all<<<(unsigned)((PREP_TOTAL + 255) / 256), 256>>>(
      w_hc, edge_c, w_hh, edge_h, embW, wxcW, wxhW, decW);

  xproj_kernel<<<dim3(8, 64, 2), 256, XPROJ_SMEM>>>(tokens, wxcB, wxhB);
  rnn_kernel<<<GRID_R, 256, RNN_SMEM>>>(outp);
  dec_kernel<<<dim3(VPAD/128, 64), 256, DEC_SMEM>>>(decB, outp);
}